// round 14
// baseline (speedup 1.0000x reference)
#include <cuda_runtime.h>
#include <cstdint>
#include <cstddef>

#define K_DIM 4096
#define O_DIM 11008
#define M_DIM 8192
#define BM 128
#define BN 128
#define THREADS 128
#define NX (O_DIM / BN)      // 86
#define K8 (K_DIM / 8)       // 512 k8-steps
#define PH 32                // panel height: halves W DRAM re-reads; WS ~83MB < L2

// fragment-permuted scratch:
// chunk(m16, k8) = 512B: lane l (g=l>>2,t=l&3) holds {A[g][t],A[g+8][t],A[g][t+4],A[g+8][t+4]}
__device__ __align__(16) float g_xp[(size_t)M_DIM * K_DIM];
// chunk(n16, k8) = 512B: lane l holds {W[g][t],W[g][t+4],W[g+8][t],W[g+8][t+4]}
__device__ __align__(16) float g_wp[(size_t)O_DIM * K_DIM];

#define MT_BYTES ((size_t)(K_DIM / 8) * 512)   // bytes per 16-row band = 262144

__device__ __forceinline__ float to_tf32(float f) {
    unsigned u;
    asm("cvt.rna.tf32.f32 %0, %1;" : "=r"(u) : "f"(f));
    return __uint_as_float(u);
}

__device__ __forceinline__ float4 ldg_nc4(const void* p) {
    float4 v;
    asm volatile("ld.global.nc.v4.f32 {%0,%1,%2,%3}, [%4];"
                 : "=f"(v.x), "=f"(v.y), "=f"(v.z), "=f"(v.w) : "l"(p));
    return v;
}

// ---------- pre-pass 1: permute x into fragment order (RNA tf32 rounding) ----------
__global__ void __launch_bounds__(256)
permute_x(const float* __restrict__ x)
{
    __shared__ float sX[64][68];
    const int tid = threadIdx.x;
    const int bk = blockIdx.x;       // 64-col K block
    const int bm = blockIdx.y;       // 64-row M block

    const int row0 = tid >> 4, c4 = tid & 15;
    #pragma unroll
    for (int i = 0; i < 4; i++) {
        const int r = row0 + i * 16;
        float4 v = *(const float4*)(x + (size_t)(bm * 64 + r) * K_DIM + bk * 64 + c4 * 4);
        float4 o = make_float4(to_tf32(v.x), to_tf32(v.y), to_tf32(v.z), to_tf32(v.w));
        *(float4*)(&sX[r][c4 * 4]) = o;
    }
    __syncthreads();

    #pragma unroll
    for (int s = 0; s < 4; s++) {
        const int gs = s * 256 + tid;
        const int chunk = gs >> 5, lane = gs & 31;
        const int k8l = chunk & 7, m16l = chunk >> 3;
        const int g = lane >> 2, t = lane & 3;
        float4 o;
        o.x = sX[m16l * 16 + g    ][k8l * 8 + t    ];
        o.y = sX[m16l * 16 + 8 + g][k8l * 8 + t    ];
        o.z = sX[m16l * 16 + g    ][k8l * 8 + t + 4];
        o.w = sX[m16l * 16 + 8 + g][k8l * 8 + t + 4];
        const size_t m16g = (size_t)bm * 4 + m16l;
        const size_t k8g  = (size_t)bk * 8 + k8l;
        ((float4*)g_xp)[(m16g * K8 + k8g) * 32 + lane] = o;
    }
}

// ---------- pre-pass 2: dequant + permute W into fragment order ----------
__global__ void __launch_bounds__(256)
permute_w(const int* __restrict__ widx, const float* __restrict__ cb)
{
    __shared__ float sW[64][68];
    __shared__ float scb[256];
    const int tid = threadIdx.x;
    scb[tid] = to_tf32(cb[tid]);
    __syncthreads();

    const int bk = blockIdx.x;       // 64-col K block
    const int bo = blockIdx.y;       // 64-row O block

    const int row0 = tid >> 4, c4 = tid & 15;
    #pragma unroll
    for (int i = 0; i < 4; i++) {
        const int r = row0 + i * 16;
        int4 v = *(const int4*)(widx + (size_t)(bo * 64 + r) * K_DIM + bk * 64 + c4 * 4);
        float4 o = make_float4(scb[v.x], scb[v.y], scb[v.z], scb[v.w]);
        *(float4*)(&sW[r][c4 * 4]) = o;
    }
    __syncthreads();

    #pragma unroll
    for (int s = 0; s < 4; s++) {
        const int gs = s * 256 + tid;
        const int chunk = gs >> 5, lane = gs & 31;
        const int k8l = chunk & 7, n16l = chunk >> 3;
        const int g = lane >> 2, t = lane & 3;
        float4 o;
        o.x = sW[n16l * 16 + g    ][k8l * 8 + t    ];
        o.y = sW[n16l * 16 + g    ][k8l * 8 + t + 4];
        o.z = sW[n16l * 16 + 8 + g][k8l * 8 + t    ];
        o.w = sW[n16l * 16 + 8 + g][k8l * 8 + t + 4];
        const size_t n16g = (size_t)bo * 4 + n16l;
        const size_t k8g  = (size_t)bk * 8 + k8l;
        ((float4*)g_wp)[(n16g * K8 + k8g) * 32 + lane] = o;
    }
}

// ---------- GEMM: no smem; TRIPLE-buffered register frags (distance-2 loads) ----------
__global__ void __launch_bounds__(THREADS, 2)
phirho_gemm_v14(const float* __restrict__ bias, float* __restrict__ out)
{
    const int tid = threadIdx.x;

    // panel rasterization
    const int bid = blockIdx.x;
    const int per_panel = PH * NX;
    const int panel = bid / per_panel;
    const int r0 = bid - panel * per_panel;
    const int by = panel * PH + (r0 % PH);
    const int bx = r0 / PH;
    const int bm = by * BM;
    const int bn = bx * BN;

    const int w = tid >> 5, lane = tid & 31;
    const int wm = (w >> 1) * 64;
    const int wn = (w & 1) * 64;
    const int g = lane >> 2, t = lane & 3;

    // per-warp fragment pointers (advance 512B per k8 step)
    const char* aPtr = (const char*)g_xp +
        ((size_t)((bm + wm) >> 4) * K8 * 512) + (size_t)lane * 16;
    const char* bPtr = (const char*)g_wp +
        ((size_t)((bn + wn) >> 4) * K8 * 512) + (size_t)lane * 16;

    float acc[4][8][4];
    #pragma unroll
    for (int i = 0; i < 4; i++)
        #pragma unroll
        for (int j = 0; j < 8; j++)
            #pragma unroll
            for (int c = 0; c < 4; c++)
                acc[i][j][c] = 0.0f;

    // three fragment buffers; step j uses buffer (j mod 3); loads run 2 steps ahead
    float4 a0[4], b0[4], a1[4], b1[4], a2[4], b2[4];

#define LD_INTO(AB, BB, OFF)                                               \
    do {                                                                   \
        _Pragma("unroll")                                                  \
        for (int mt = 0; mt < 4; mt++) {                                   \
            AB[mt] = ldg_nc4(aPtr + (size_t)mt * MT_BYTES + (OFF));        \
            BB[mt] = ldg_nc4(bPtr + (size_t)mt * MT_BYTES + (OFF));        \
        }                                                                  \
    } while (0)

#define MMAS(AB, BB)                                                       \
    do {                                                                   \
        _Pragma("unroll")                                                  \
        for (int mt = 0; mt < 4; mt++) {                                   \
            const unsigned ra0 = __float_as_uint(AB[mt].x);                \
            const unsigned ra1 = __float_as_uint(AB[mt].y);                \
            const unsigned ra2 = __float_as_uint(AB[mt].z);                \
            const unsigned ra3 = __float_as_uint(AB[mt].w);                \
            _Pragma("unroll")                                              \
            for (int nt = 0; nt < 8; nt++) {                               \
                const int np = nt >> 1;                                    \
                const unsigned rb0 = (nt & 1) ? __float_as_uint(BB[np].z)  \
                                              : __float_as_uint(BB[np].x); \
                const unsigned rb1 = (nt & 1) ? __float_as_uint(BB[np].w)  \
                                              : __float_as_uint(BB[np].y); \
                asm volatile(                                              \
                    "mma.sync.aligned.m16n8k8.row.col.f32.tf32.tf32.f32 "  \
                    "{%0,%1,%2,%3}, {%4,%5,%6,%7}, {%8,%9}, {%0,%1,%2,%3};\n" \
                    : "+f"(acc[mt][nt][0]), "+f"(acc[mt][nt][1]),          \
                      "+f"(acc[mt][nt][2]), "+f"(acc[mt][nt][3])           \
                    : "r"(ra0), "r"(ra1), "r"(ra2), "r"(ra3),              \
                      "r"(rb0), "r"(rb1));                                 \
            }                                                              \
        }                                                                  \
    } while (0)

    // prologue: steps 0,1 into buffers 0,1
    LD_INTO(a0, b0, 0);
    LD_INTO(a1, b1, 512);

    // main loop: 170 iterations x 3 steps = 510; step j consumes buf (j%3),
    // and loads j+2 into buf ((j+2)%3). Pointers advance 1536B per iteration.
    for (int it = 0; it < 170; it++) {
        LD_INTO(a2, b2, 1024);   // step j+2 -> buf2
        MMAS(a0, b0);            // step j   (buf0)
        LD_INTO(a0, b0, 1536);   // step j+3 -> buf0
        MMAS(a1, b1);            // step j+1 (buf1)
        LD_INTO(a1, b1, 2048);   // step j+4 -> buf1
        MMAS(a2, b2);            // step j+2 (buf2)
        aPtr += 1536;
        bPtr += 1536;
        if ((it & 15) == 15) __syncthreads();   // re-converge warps for L1 reuse
    }
    // tail: steps 510 (buf0), 511 (buf1) — already loaded in final iteration
    MMAS(a0, b0);
    MMAS(a1, b1);

    // epilogue: bias add + STREAMING fp32 stores (don't evict L2-resident W)
    #pragma unroll
    for (int nt = 0; nt < 8; nt++) {
        const int col = bn + wn + nt * 8 + t * 2;
        const float vb0 = __ldg(bias + col);
        const float vb1 = __ldg(bias + col + 1);
        #pragma unroll
        for (int mt = 0; mt < 4; mt++) {
            const int row = bm + wm + mt * 16 + g;
            float2 v0 = make_float2(acc[mt][nt][0] + vb0, acc[mt][nt][1] + vb1);
            float2 v1 = make_float2(acc[mt][nt][2] + vb0, acc[mt][nt][3] + vb1);
            __stcs((float2*)(out + (size_t)row       * O_DIM + col), v0);
            __stcs((float2*)(out + (size_t)(row + 8) * O_DIM + col), v1);
        }
    }
}

extern "C" void kernel_launch(void* const* d_in, const int* in_sizes, int n_in,
                              void* d_out, int out_size) {
    const float* x    = (const float*)d_in[0];
    const int*   widx = (const int*)  d_in[1];
    const float* cb   = (const float*)d_in[2];
    const float* bias = (const float*)d_in[3];
    float* out = (float*)d_out;

    const int ntok = in_sizes[0] / K_DIM;   // 8192
    const int ny = ntok / BM;               // 64

    // pre-pass: permute x and dequant+permute W into fragment layouts
    permute_x<<<dim3(K_DIM / 64, ntok / 64), 256>>>(x);
    permute_w<<<dim3(K_DIM / 64, O_DIM / 64), 256>>>(widx, cb);

    // GEMM
    dim3 grid(NX * ny);                     // 5504
    phirho_gemm_v14<<<grid, THREADS>>>(bias, out);
}

// round 15
// speedup vs baseline: 1.0147x; 1.0147x over previous
#include <cuda_runtime.h>
#include <cstdint>
#include <cstddef>

#define K_DIM 4096
#define O_DIM 11008
#define M_DIM 8192
#define BM 128
#define BN 128
#define THREADS 128
#define NX (O_DIM / BN)      // 86
#define K8 (K_DIM / 8)       // 512 k8-steps
#define PH 16                // panel height (v13 value — PH=32 regressed in R14)

// fragment-permuted scratch:
// chunk(m16, k8) = 512B: lane l (g=l>>2,t=l&3) holds {A[g][t],A[g+8][t],A[g][t+4],A[g+8][t+4]}
__device__ __align__(16) float g_xp[(size_t)M_DIM * K_DIM];
// chunk(n16, k8) = 512B: lane l holds {W[g][t],W[g][t+4],W[g+8][t],W[g+8][t+4]}
__device__ __align__(16) float g_wp[(size_t)O_DIM * K_DIM];

#define MT_BYTES ((size_t)(K_DIM / 8) * 512)   // bytes per 16-row band = 262144

__device__ __forceinline__ float to_tf32(float f) {
    unsigned u;
    asm("cvt.rna.tf32.f32 %0, %1;" : "=r"(u) : "f"(f));
    return __uint_as_float(u);
}

__device__ __forceinline__ float4 ldg_nc4(const void* p) {
    float4 v;
    asm volatile("ld.global.nc.v4.f32 {%0,%1,%2,%3}, [%4];"
                 : "=f"(v.x), "=f"(v.y), "=f"(v.z), "=f"(v.w) : "l"(p));
    return v;
}

// ---------- fused pre-pass: z=0 permutes x (RNA tf32), z=1 dequant+permutes W ----------
__global__ void __launch_bounds__(256)
permute_xw(const float* __restrict__ x,
           const int*   __restrict__ widx,
           const float* __restrict__ cb)
{
    __shared__ float sT[64][68];
    __shared__ float scb[256];
    const int tid = threadIdx.x;
    const int bk = blockIdx.x;       // 64-col K block
    const int br = blockIdx.y;       // 64-row block (M or O)
    const int job = blockIdx.z;      // 0 = x, 1 = W

    const int row0 = tid >> 4, c4 = tid & 15;

    if (job == 0) {
        if (br >= M_DIM / 64) return;
        #pragma unroll
        for (int i = 0; i < 4; i++) {
            const int r = row0 + i * 16;
            float4 v = *(const float4*)(x + (size_t)(br * 64 + r) * K_DIM + bk * 64 + c4 * 4);
            float4 o = make_float4(to_tf32(v.x), to_tf32(v.y), to_tf32(v.z), to_tf32(v.w));
            *(float4*)(&sT[r][c4 * 4]) = o;
        }
        __syncthreads();
        #pragma unroll
        for (int s = 0; s < 4; s++) {
            const int gs = s * 256 + tid;
            const int chunk = gs >> 5, lane = gs & 31;
            const int k8l = chunk & 7, m16l = chunk >> 3;
            const int g = lane >> 2, t = lane & 3;
            float4 o;
            o.x = sT[m16l * 16 + g    ][k8l * 8 + t    ];
            o.y = sT[m16l * 16 + 8 + g][k8l * 8 + t    ];
            o.z = sT[m16l * 16 + g    ][k8l * 8 + t + 4];
            o.w = sT[m16l * 16 + 8 + g][k8l * 8 + t + 4];
            const size_t m16g = (size_t)br * 4 + m16l;
            const size_t k8g  = (size_t)bk * 8 + k8l;
            ((float4*)g_xp)[(m16g * K8 + k8g) * 32 + lane] = o;
        }
    } else {
        scb[tid] = to_tf32(cb[tid]);
        __syncthreads();
        #pragma unroll
        for (int i = 0; i < 4; i++) {
            const int r = row0 + i * 16;
            int4 v = *(const int4*)(widx + (size_t)(br * 64 + r) * K_DIM + bk * 64 + c4 * 4);
            float4 o = make_float4(scb[v.x], scb[v.y], scb[v.z], scb[v.w]);
            *(float4*)(&sT[r][c4 * 4]) = o;
        }
        __syncthreads();
        #pragma unroll
        for (int s = 0; s < 4; s++) {
            const int gs = s * 256 + tid;
            const int chunk = gs >> 5, lane = gs & 31;
            const int k8l = chunk & 7, n16l = chunk >> 3;
            const int g = lane >> 2, t = lane & 3;
            float4 o;
            o.x = sT[n16l * 16 + g    ][k8l * 8 + t    ];
            o.y = sT[n16l * 16 + g    ][k8l * 8 + t + 4];
            o.z = sT[n16l * 16 + 8 + g][k8l * 8 + t    ];
            o.w = sT[n16l * 16 + 8 + g][k8l * 8 + t + 4];
            const size_t n16g = (size_t)br * 4 + n16l;
            const size_t k8g  = (size_t)bk * 8 + k8l;
            ((float4*)g_wp)[(n16g * K8 + k8g) * 32 + lane] = o;
        }
    }
}

// ---------- GEMM: no smem; TRIPLE-buffered register frags (distance-2 loads) ----------
__global__ void __launch_bounds__(THREADS, 2)
phirho_gemm_v15(const float* __restrict__ bias, float* __restrict__ out)
{
    const int tid = threadIdx.x;

    // panel rasterization
    const int bid = blockIdx.x;
    const int per_panel = PH * NX;
    const int panel = bid / per_panel;
    const int r0 = bid - panel * per_panel;
    const int by = panel * PH + (r0 % PH);
    const int bx = r0 / PH;
    const int bm = by * BM;
    const int bn = bx * BN;

    const int w = tid >> 5, lane = tid & 31;
    const int wm = (w >> 1) * 64;
    const int wn = (w & 1) * 64;
    const int g = lane >> 2, t = lane & 3;

    // per-warp fragment pointers (advance 512B per k8 step)
    const char* aPtr = (const char*)g_xp +
        ((size_t)((bm + wm) >> 4) * K8 * 512) + (size_t)lane * 16;
    const char* bPtr = (const char*)g_wp +
        ((size_t)((bn + wn) >> 4) * K8 * 512) + (size_t)lane * 16;

    float acc[4][8][4];
    #pragma unroll
    for (int i = 0; i < 4; i++)
        #pragma unroll
        for (int j = 0; j < 8; j++)
            #pragma unroll
            for (int c = 0; c < 4; c++)
                acc[i][j][c] = 0.0f;

    // three fragment buffers; step j uses buffer (j mod 3); loads run 2 steps ahead
    float4 a0[4], b0[4], a1[4], b1[4], a2[4], b2[4];

#define LD_INTO(AB, BB, OFF)                                               \
    do {                                                                   \
        _Pragma("unroll")                                                  \
        for (int mt = 0; mt < 4; mt++) {                                   \
            AB[mt] = ldg_nc4(aPtr + (size_t)mt * MT_BYTES + (OFF));        \
            BB[mt] = ldg_nc4(bPtr + (size_t)mt * MT_BYTES + (OFF));        \
        }                                                                  \
    } while (0)

#define MMAS(AB, BB)                                                       \
    do {                                                                   \
        _Pragma("unroll")                                                  \
        for (int mt = 0; mt < 4; mt++) {                                   \
            const unsigned ra0 = __float_as_uint(AB[mt].x);                \
            const unsigned ra1 = __float_as_uint(AB[mt].y);                \
            const unsigned ra2 = __float_as_uint(AB[mt].z);                \
            const unsigned ra3 = __float_as_uint(AB[mt].w);                \
            _Pragma("unroll")                                              \
            for (int nt = 0; nt < 8; nt++) {                               \
                const int np = nt >> 1;                                    \
                const unsigned rb0 = (nt & 1) ? __float_as_uint(BB[np].z)  \
                                              : __float_as_uint(BB[np].x); \
                const unsigned rb1 = (nt & 1) ? __float_as_uint(BB[np].w)  \
                                              : __float_as_uint(BB[np].y); \
                asm volatile(                                              \
                    "mma.sync.aligned.m16n8k8.row.col.f32.tf32.tf32.f32 "  \
                    "{%0,%1,%2,%3}, {%4,%5,%6,%7}, {%8,%9}, {%0,%1,%2,%3};\n" \
                    : "+f"(acc[mt][nt][0]), "+f"(acc[mt][nt][1]),          \
                      "+f"(acc[mt][nt][2]), "+f"(acc[mt][nt][3])           \
                    : "r"(ra0), "r"(ra1), "r"(ra2), "r"(ra3),              \
                      "r"(rb0), "r"(rb1));                                 \
            }                                                              \
        }                                                                  \
    } while (0)

    // prologue: steps 0,1 into buffers 0,1
    LD_INTO(a0, b0, 0);
    LD_INTO(a1, b1, 512);

    // main loop: 170 iterations x 3 steps = 510; step j consumes buf (j%3),
    // and loads j+2 into buf ((j+2)%3). Pointers advance 1536B per iteration.
    for (int it = 0; it < 170; it++) {
        LD_INTO(a2, b2, 1024);   // step j+2 -> buf2
        MMAS(a0, b0);            // step j   (buf0)
        LD_INTO(a0, b0, 1536);   // step j+3 -> buf0
        MMAS(a1, b1);            // step j+1 (buf1)
        LD_INTO(a1, b1, 2048);   // step j+4 -> buf1
        MMAS(a2, b2);            // step j+2 (buf2)
        aPtr += 1536;
        bPtr += 1536;
        if ((it & 15) == 15) __syncthreads();   // re-converge warps for L1 reuse
    }
    // tail: steps 510 (buf0), 511 (buf1) — already loaded in final iteration
    MMAS(a0, b0);
    MMAS(a1, b1);

    // epilogue: bias add + streaming fp32 stores (don't evict L2-resident W)
    #pragma unroll
    for (int nt = 0; nt < 8; nt++) {
        const int col = bn + wn + nt * 8 + t * 2;
        const float vb0 = __ldg(bias + col);
        const float vb1 = __ldg(bias + col + 1);
        #pragma unroll
        for (int mt = 0; mt < 4; mt++) {
            const int row = bm + wm + mt * 16 + g;
            float2 v0 = make_float2(acc[mt][nt][0] + vb0, acc[mt][nt][1] + vb1);
            float2 v1 = make_float2(acc[mt][nt][2] + vb0, acc[mt][nt][3] + vb1);
            __stcs((float2*)(out + (size_t)row       * O_DIM + col), v0);
            __stcs((float2*)(out + (size_t)(row + 8) * O_DIM + col), v1);
        }
    }
}

extern "C" void kernel_launch(void* const* d_in, const int* in_sizes, int n_in,
                              void* d_out, int out_size) {
    const float* x    = (const float*)d_in[0];
    const int*   widx = (const int*)  d_in[1];
    const float* cb   = (const float*)d_in[2];
    const float* bias = (const float*)d_in[3];
    float* out = (float*)d_out;

    const int ntok = in_sizes[0] / K_DIM;   // 8192
    const int ny = ntok / BM;               // 64

    // fused pre-pass: z=0 permutes x (128 row-blocks), z=1 dequant+permutes W (172)
    dim3 pgrid(K_DIM / 64, O_DIM / 64, 2);  // y sized for W job; x job guards
    permute_xw<<<pgrid, 256>>>(x, widx, cb);

    // GEMM
    dim3 grid(NX * ny);                     // 5504
    phirho_gemm_v15<<<grid, THREADS>>>(bias, out);
}

// round 16
// speedup vs baseline: 1.9370x; 1.9089x over previous
#include <cuda_runtime.h>
#include <cuda_fp16.h>
#include <cstdint>
#include <cstddef>

#define K_DIM 4096
#define O_DIM 11008
#define M_DIM 8192
#define BM 128
#define BN 128
#define THREADS 128
#define NX (O_DIM / BN)      // 86
#define K16 (K_DIM / 16)     // 256 k16-steps
#define PH 16                // panel height (best measured)

// fragment-permuted fp16 scratch:
// A chunk (m16, k16) = 512B: lane l (g=l>>2,t=l&3) holds uint4 =
//   { h2(A[g][2t],A[g][2t+1]), h2(A[g+8][2t],A[g+8][2t+1]),
//     h2(A[g][2t+8],A[g][2t+9]), h2(A[g+8][2t+8],A[g+8][2t+9]) }
__device__ __align__(16) __half g_xp[(size_t)M_DIM * K_DIM];   // 64MB
// W chunk (n16, k16) = 512B: lane l holds uint4 =
//   { h2(W[b+g][2t],[2t+1]), h2(W[b+g][2t+8],[2t+9]),
//     h2(W[b+8+g][2t],[2t+1]), h2(W[b+8+g][2t+8],[2t+9]) }   (b = n16 base)
__device__ __align__(16) __half g_wp[(size_t)O_DIM * K_DIM];   // 88MB

#define MT_BYTES ((size_t)K16 * 512)   // bytes per 16-row band = 131072

__device__ __forceinline__ unsigned packh2(float lo, float hi) {
    __half2 h = __floats2half2_rn(lo, hi);   // .x = lo (low 16 bits)
    return *reinterpret_cast<unsigned*>(&h);
}

__device__ __forceinline__ uint4 ldg_nc4u(const void* p) {
    uint4 v;
    asm volatile("ld.global.nc.v4.u32 {%0,%1,%2,%3}, [%4];"
                 : "=r"(v.x), "=r"(v.y), "=r"(v.z), "=r"(v.w) : "l"(p));
    return v;
}

// ---------- fused pre-pass: z=0 permutes x -> fp16 frags, z=1 dequant W -> fp16 frags ----------
__global__ void __launch_bounds__(256)
permute_xw(const float* __restrict__ x,
           const int*   __restrict__ widx,
           const float* __restrict__ cb)
{
    __shared__ float sT[64][68];
    __shared__ float scb[256];
    const int tid = threadIdx.x;
    const int bk = blockIdx.x;       // 64-col K block (4 k16 chunks)
    const int br = blockIdx.y;       // 64-row block (M or O; 4 16-row chunks)
    const int job = blockIdx.z;      // 0 = x, 1 = W

    const int row0 = tid >> 4, c4 = tid & 15;

    if (job == 0) {
        if (br >= M_DIM / 64) return;
        #pragma unroll
        for (int i = 0; i < 4; i++) {
            const int r = row0 + i * 16;
            float4 v = *(const float4*)(x + (size_t)(br * 64 + r) * K_DIM + bk * 64 + c4 * 4);
            *(float4*)(&sT[r][c4 * 4]) = v;
        }
        __syncthreads();
        #pragma unroll
        for (int s = 0; s < 2; s++) {
            const int gs = s * 256 + tid;          // 0..511 lane-slots
            const int chunk = gs >> 5, lane = gs & 31;
            const int m16l = chunk >> 2, k16l = chunk & 3;
            const int g = lane >> 2, t = lane & 3;
            const int r0 = m16l * 16 + g, r1 = r0 + 8;
            const int c0 = k16l * 16 + 2 * t;
            uint4 u;
            u.x = packh2(sT[r0][c0    ], sT[r0][c0 + 1]);
            u.y = packh2(sT[r1][c0    ], sT[r1][c0 + 1]);
            u.z = packh2(sT[r0][c0 + 8], sT[r0][c0 + 9]);
            u.w = packh2(sT[r1][c0 + 8], sT[r1][c0 + 9]);
            const size_t m16g = (size_t)br * 4 + m16l;
            const size_t k16g = (size_t)bk * 4 + k16l;
            ((uint4*)g_xp)[(m16g * K16 + k16g) * 32 + lane] = u;
        }
    } else {
        scb[tid] = cb[tid];
        __syncthreads();
        #pragma unroll
        for (int i = 0; i < 4; i++) {
            const int r = row0 + i * 16;
            int4 v = *(const int4*)(widx + (size_t)(br * 64 + r) * K_DIM + bk * 64 + c4 * 4);
            float4 o = make_float4(scb[v.x], scb[v.y], scb[v.z], scb[v.w]);
            *(float4*)(&sT[r][c4 * 4]) = o;
        }
        __syncthreads();
        #pragma unroll
        for (int s = 0; s < 2; s++) {
            const int gs = s * 256 + tid;
            const int chunk = gs >> 5, lane = gs & 31;
            const int n16l = chunk >> 2, k16l = chunk & 3;
            const int g = lane >> 2, t = lane & 3;
            const int r0 = n16l * 16 + g, r1 = r0 + 8;
            const int c0 = k16l * 16 + 2 * t;
            uint4 u;
            u.x = packh2(sT[r0][c0    ], sT[r0][c0 + 1]);
            u.y = packh2(sT[r0][c0 + 8], sT[r0][c0 + 9]);
            u.z = packh2(sT[r1][c0    ], sT[r1][c0 + 1]);
            u.w = packh2(sT[r1][c0 + 8], sT[r1][c0 + 9]);
            const size_t n16g = (size_t)br * 4 + n16l;
            const size_t k16g = (size_t)bk * 4 + k16l;
            ((uint4*)g_wp)[(n16g * K16 + k16g) * 32 + lane] = u;
        }
    }
}

// ---------- GEMM: fp16 m16n8k16, no smem, TRIPLE-buffered frags (distance-2) ----------
__global__ void __launch_bounds__(THREADS, 2)
phirho_gemm_v16(const float* __restrict__ bias, float* __restrict__ out)
{
    const int tid = threadIdx.x;

    // panel rasterization
    const int bid = blockIdx.x;
    const int per_panel = PH * NX;
    const int panel = bid / per_panel;
    const int r0 = bid - panel * per_panel;
    const int by = panel * PH + (r0 % PH);
    const int bx = r0 / PH;
    const int bm = by * BM;
    const int bn = bx * BN;

    const int w = tid >> 5, lane = tid & 31;
    const int wm = (w >> 1) * 64;
    const int wn = (w & 1) * 64;
    const int g = lane >> 2, t = lane & 3;

    // per-warp fragment pointers (advance 512B per k16 step)
    const char* aPtr = (const char*)g_xp +
        ((size_t)((bm + wm) >> 4) * MT_BYTES) + (size_t)lane * 16;
    const char* bPtr = (const char*)g_wp +
        ((size_t)((bn + wn) >> 4) * MT_BYTES) + (size_t)lane * 16;

    float acc[4][8][4];
    #pragma unroll
    for (int i = 0; i < 4; i++)
        #pragma unroll
        for (int j = 0; j < 8; j++)
            #pragma unroll
            for (int c = 0; c < 4; c++)
                acc[i][j][c] = 0.0f;

    // three fragment buffers; loads run 2 steps ahead
    uint4 a0[4], b0[4], a1[4], b1[4], a2[4], b2[4];

#define LD_INTO(AB, BB, OFF)                                               \
    do {                                                                   \
        _Pragma("unroll")                                                  \
        for (int mt = 0; mt < 4; mt++) {                                   \
            AB[mt] = ldg_nc4u(aPtr + (size_t)mt * MT_BYTES + (OFF));       \
            BB[mt] = ldg_nc4u(bPtr + (size_t)mt * MT_BYTES + (OFF));       \
        }                                                                  \
    } while (0)

#define MMAS(AB, BB)                                                       \
    do {                                                                   \
        _Pragma("unroll")                                                  \
        for (int mt = 0; mt < 4; mt++) {                                   \
            const unsigned ra0 = AB[mt].x;                                 \
            const unsigned ra1 = AB[mt].y;                                 \
            const unsigned ra2 = AB[mt].z;                                 \
            const unsigned ra3 = AB[mt].w;                                 \
            _Pragma("unroll")                                              \
            for (int nt = 0; nt < 8; nt++) {                               \
                const int np = nt >> 1;                                    \
                const unsigned rb0 = (nt & 1) ? BB[np].z : BB[np].x;       \
                const unsigned rb1 = (nt & 1) ? BB[np].w : BB[np].y;       \
                asm volatile(                                              \
                    "mma.sync.aligned.m16n8k16.row.col.f32.f16.f16.f32 "   \
                    "{%0,%1,%2,%3}, {%4,%5,%6,%7}, {%8,%9}, {%0,%1,%2,%3};\n" \
                    : "+f"(acc[mt][nt][0]), "+f"(acc[mt][nt][1]),          \
                      "+f"(acc[mt][nt][2]), "+f"(acc[mt][nt][3])           \
                    : "r"(ra0), "r"(ra1), "r"(ra2), "r"(ra3),              \
                      "r"(rb0), "r"(rb1));                                 \
            }                                                              \
        }                                                                  \
    } while (0)

    // prologue: steps 0,1 into buffers 0,1
    LD_INTO(a0, b0, 0);
    LD_INTO(a1, b1, 512);

    // main loop: 84 iterations x 3 steps = 252; tail handles steps 252..255.
    for (int it = 0; it < 84; it++) {
        LD_INTO(a2, b2, 1024);   // step j+2 -> buf2
        MMAS(a0, b0);            // step j   (buf0)
        LD_INTO(a0, b0, 1536);   // step j+3 -> buf0
        MMAS(a1, b1);            // step j+1 (buf1)
        LD_INTO(a1, b1, 2048);   // step j+4 -> buf1
        MMAS(a2, b2);            // step j+2 (buf2)
        aPtr += 1536;
        bPtr += 1536;
        if ((it & 15) == 15) __syncthreads();   // re-converge warps for L1 reuse
    }
    // tail: steps 252..255 (buffers hold 252(a0),253(a1); pointers at step-252 base)
    LD_INTO(a2, b2, 1024);       // step 254
    MMAS(a0, b0);                // step 252
    LD_INTO(a0, b0, 1536);       // step 255
    MMAS(a1, b1);                // step 253
    MMAS(a2, b2);                // step 254
    MMAS(a0, b0);                // step 255

    // epilogue: bias add + streaming fp32 stores
    #pragma unroll
    for (int nt = 0; nt < 8; nt++) {
        const int col = bn + wn + nt * 8 + t * 2;
        const float vb0 = __ldg(bias + col);
        const float vb1 = __ldg(bias + col + 1);
        #pragma unroll
        for (int mt = 0; mt < 4; mt++) {
            const int row = bm + wm + mt * 16 + g;
            float2 v0 = make_float2(acc[mt][nt][0] + vb0, acc[mt][nt][1] + vb1);
            float2 v1 = make_float2(acc[mt][nt][2] + vb0, acc[mt][nt][3] + vb1);
            __stcs((float2*)(out + (size_t)row       * O_DIM + col), v0);
            __stcs((float2*)(out + (size_t)(row + 8) * O_DIM + col), v1);
        }
    }
}

extern "C" void kernel_launch(void* const* d_in, const int* in_sizes, int n_in,
                              void* d_out, int out_size) {
    const float* x    = (const float*)d_in[0];
    const int*   widx = (const int*)  d_in[1];
    const float* cb   = (const float*)d_in[2];
    const float* bias = (const float*)d_in[3];
    float* out = (float*)d_out;

    const int ntok = in_sizes[0] / K_DIM;   // 8192
    const int ny = ntok / BM;               // 64

    // fused pre-pass: z=0 permutes x (128 row-blocks), z=1 dequant+permutes W (172)
    dim3 pgrid(K_DIM / 64, O_DIM / 64, 2);  // y sized for W job; x job guards
    permute_xw<<<pgrid, 256>>>(x, widx, cb);

    // GEMM (fp16 tensor cores)
    dim3 grid(NX * ny);                     // 5504
    phirho_gemm_v16<<<grid, THREADS>>>(bias, out);
}